// round 4
// baseline (speedup 1.0000x reference)
#include <cuda_runtime.h>
#include <cuda_bf16.h>

#define BB 16
#define SS 4096
#define DD 1024

#define ATT_SPLIT 64   // 64-row tiles; 16*64 = 1024 units, 512 blocks x 2 units

// ---------------- scratch (device globals; no allocations) ----------------
__device__ float g_q[BB * DD];
__device__ float g_qk[BB * DD];
__device__ float g_esum_part[BB][ATT_SPLIT];
__device__ float g_ctx_part[ATT_SPLIT][BB * DD];
__device__ float g_ctx[BB * DD];

// ---------------------------------------------------------------------------
// K1 / K5: full batched GEMV in one kernel (no split-K, no reduce kernel).
// out[b, h] = sum_j X[b, j] * W[j, h]
// grid 64, block 256: block owns 16 columns h; thread = (b = tid>>4, h = tid&15).
// W row segment per block = 64 B -> coalesced; W read exactly once chip-wide.
// Xsel: 0 -> X param (query), 1 -> g_ctx.
// ---------------------------------------------------------------------------
__global__ void __launch_bounds__(256) gemv16_kernel(const float* __restrict__ X,
                                                     const float* __restrict__ W,
                                                     float* __restrict__ out,
                                                     int Xsel) {
    const float* Xp = (Xsel == 0) ? X : g_ctx;
    const int h = blockIdx.x * 16 + (threadIdx.x & 15);
    const int b = threadIdx.x >> 4;

    __shared__ __align__(16) float xs[BB][512];

    float acc = 0.f;
    for (int j0 = 0; j0 < DD; j0 += 512) {
        __syncthreads();
        for (int t = threadIdx.x; t < BB * 128; t += 256) {   // 2048 float4
            int bb = t >> 7, jj = t & 127;
            ((float4*)xs[bb])[jj] = ((const float4*)(Xp + bb * DD + j0))[jj];
        }
        __syncthreads();

        float a0 = 0.f, a1 = 0.f, a2 = 0.f, a3 = 0.f;
#pragma unroll 4
        for (int jj = 0; jj < 512; jj += 4) {
            a0 += xs[b][jj]     * W[(size_t)(j0 + jj)     * DD + h];
            a1 += xs[b][jj + 1] * W[(size_t)(j0 + jj + 1) * DD + h];
            a2 += xs[b][jj + 2] * W[(size_t)(j0 + jj + 2) * DD + h];
            a3 += xs[b][jj + 3] * W[(size_t)(j0 + jj + 3) * DD + h];
        }
        acc += (a0 + a1) + (a2 + a3);
    }
    out[b * DD + h] = acc;
}

// ---------------------------------------------------------------------------
// K2: qk[b,i] = sum_h Wk[i,h] * q[b,h]   (warp per row i, float4 loads)
// grid DD/8 = 128, block 256 (8 warps)
// ---------------------------------------------------------------------------
__global__ void qk_kernel(const float* __restrict__ Wk) {
    const int warp = threadIdx.x >> 5;
    const int lane = threadIdx.x & 31;
    const int i = blockIdx.x * 8 + warp;

    __shared__ __align__(16) float qs[BB][DD];
    for (int t = threadIdx.x; t < BB * DD / 4; t += 256) {
        ((float4*)&qs[0][0])[t] = ((const float4*)g_q)[t];
    }
    __syncthreads();

    const float4* wrow = (const float4*)(Wk + (size_t)i * DD);

    float acc[BB];
#pragma unroll
    for (int b = 0; b < BB; b++) acc[b] = 0.f;

#pragma unroll
    for (int c = 0; c < DD / 4; c += 32) {
        float4 w4 = wrow[c + lane];
        int h = (c + lane) * 4;
#pragma unroll
        for (int b = 0; b < BB; b++) {
            acc[b] += w4.x * qs[b][h] + w4.y * qs[b][h + 1]
                    + w4.z * qs[b][h + 2] + w4.w * qs[b][h + 3];
        }
    }
#pragma unroll
    for (int b = 0; b < BB; b++) {
        float v = acc[b];
#pragma unroll
        for (int o = 16; o > 0; o >>= 1) v += __shfl_down_sync(0xffffffffu, v, o);
        if (lane == 0) g_qk[b * DD + i] = v;
    }
}

// ---------------------------------------------------------------------------
// K3: fused attention. grid 512, block 256.
// Block (b = blk>>5, t0 = blk&31) processes tiles t0 and t0+32 of batch b.
// All 512 blocks resident -> single uniform wave, no tail.
// Phase A: 8 rows/warp as 2 groups of 4 concurrent streams -> exp weights.
// Phase B: unnormalized weighted value accumulation -> g_ctx_part.
// ---------------------------------------------------------------------------
__global__ void __launch_bounds__(256) attn_fused_kernel(const float* __restrict__ key,
                                                         const float* __restrict__ value) {
    const int b  = blockIdx.x >> 5;
    const int t0 = blockIdx.x & 31;
    const int warp = threadIdx.x >> 5;
    const int lane = threadIdx.x & 31;

    __shared__ __align__(16) float qk_s[DD];
    __shared__ float w_s[64];
    __shared__ float red[8];

    ((float4*)qk_s)[threadIdx.x] = ((const float4*)(g_qk + b * DD))[threadIdx.x];
    const float4* qrow = (const float4*)qk_s;

#pragma unroll
    for (int half = 0; half < 2; half++) {
        const int tile = t0 + half * 32;
        const int s0 = tile * 64;
        __syncthreads();   // qk_s ready (half 0) / w_s no longer read (half 1)

        const float4* kbase = (const float4*)(key + ((size_t)b * SS + s0) * DD);

        // ---- Phase A: 2 groups of 4 rows per warp ----
        float esum = 0.f;
#pragma unroll
        for (int g = 0; g < 2; g++) {
            const int r = warp * 8 + g * 4;
            const float4* k0 = kbase + (size_t)(r + 0) * (DD / 4);
            const float4* k1 = kbase + (size_t)(r + 1) * (DD / 4);
            const float4* k2 = kbase + (size_t)(r + 2) * (DD / 4);
            const float4* k3 = kbase + (size_t)(r + 3) * (DD / 4);

            float a0 = 0.f, a1 = 0.f, a2 = 0.f, a3 = 0.f;
#pragma unroll
            for (int c = 0; c < DD / 4; c += 32) {
                float4 q4 = qrow[c + lane];
                float4 ka = __ldcs(&k0[c + lane]);
                float4 kb = __ldcs(&k1[c + lane]);
                float4 kc = __ldcs(&k2[c + lane]);
                float4 kd = __ldcs(&k3[c + lane]);
                a0 += ka.x * q4.x + ka.y * q4.y + ka.z * q4.z + ka.w * q4.w;
                a1 += kb.x * q4.x + kb.y * q4.y + kb.z * q4.z + kb.w * q4.w;
                a2 += kc.x * q4.x + kc.y * q4.y + kc.z * q4.z + kc.w * q4.w;
                a3 += kd.x * q4.x + kd.y * q4.y + kd.z * q4.z + kd.w * q4.w;
            }
#pragma unroll
            for (int o = 16; o > 0; o >>= 1) {
                a0 += __shfl_down_sync(0xffffffffu, a0, o);
                a1 += __shfl_down_sync(0xffffffffu, a1, o);
                a2 += __shfl_down_sync(0xffffffffu, a2, o);
                a3 += __shfl_down_sync(0xffffffffu, a3, o);
            }
            if (lane == 0) {
                float e0 = expf(a0 * 0.03125f);   // 1/sqrt(1024); bounded, no max shift
                float e1 = expf(a1 * 0.03125f);
                float e2 = expf(a2 * 0.03125f);
                float e3 = expf(a3 * 0.03125f);
                w_s[r + 0] = e0; w_s[r + 1] = e1;
                w_s[r + 2] = e2; w_s[r + 3] = e3;
                esum += (e0 + e1) + (e2 + e3);
            }
        }
        if (lane == 0) red[warp] = esum;
        __syncthreads();

        if (threadIdx.x == 0) {
            float s = 0.f;
#pragma unroll
            for (int w = 0; w < 8; w++) s += red[w];
            g_esum_part[b][tile] = s;
        }

        // ---- Phase B: thread owns one float4 of 1024 output dims ----
        const float4* vbase = (const float4*)(value + ((size_t)b * SS + s0) * DD);
        float4 acc = make_float4(0.f, 0.f, 0.f, 0.f);
#pragma unroll 16
        for (int ss = 0; ss < 64; ss++) {
            float w = w_s[ss];
            float4 v = __ldcs(&vbase[(size_t)ss * (DD / 4) + threadIdx.x]);
            acc.x += w * v.x; acc.y += w * v.y; acc.z += w * v.z; acc.w += w * v.w;
        }
        ((float4*)g_ctx_part[tile])[b * (DD / 4) + threadIdx.x] = acc;
    }
}

// ---------------------------------------------------------------------------
// K4: ctx reduce + softmax normalization.
// grid 64, block 256. Each block covers 256 consecutive idx -> single b.
// ---------------------------------------------------------------------------
__global__ void reduce_ctx_kernel() {
    const int idx = blockIdx.x * 256 + threadIdx.x;
    const int b = idx >> 10;   // DD = 1024; whole block shares one b

    __shared__ float er[64];
    if (threadIdx.x < 64) er[threadIdx.x] = g_esum_part[b][threadIdx.x];
    __syncthreads();
    for (int o = 32; o > 0; o >>= 1) {
        if (threadIdx.x < o) er[threadIdx.x] += er[threadIdx.x + o];
        __syncthreads();
    }
    const float inv = 1.f / er[0];

    float s = 0.f;
#pragma unroll
    for (int k = 0; k < ATT_SPLIT; k++) s += g_ctx_part[k][idx];
    g_ctx[idx] = s * inv;
}

// ---------------------------------------------------------------------------
extern "C" void kernel_launch(void* const* d_in, const int* in_sizes, int n_in,
                              void* d_out, int out_size) {
    const float* key   = (const float*)d_in[0];
    const float* query = (const float*)d_in[1];
    const float* value = (const float*)d_in[2];
    const float* Wk    = (const float*)d_in[3];
    const float* Wq    = (const float*)d_in[4];
    const float* Wv    = (const float*)d_in[5];
    float* out = (float*)d_out;

    float* d_q;
    cudaGetSymbolAddress((void**)&d_q, g_q);

    // q = query @ Wq  (single kernel)
    gemv16_kernel<<<DD / 16, 256>>>(query, Wq, d_q, 0);
    // qk[b] = Wk @ q[b]
    qk_kernel<<<DD / 8, 256>>>(Wk);
    // fused: scores -> exp -> weighted value partials (both big passes)
    attn_fused_kernel<<<512, 256>>>(key, value);
    // ctx = (sum partials) / (sum exp)
    reduce_ctx_kernel<<<BB * DD / 256, 256>>>();
    // out = ctx @ Wv  (single kernel, writes d_out)
    gemv16_kernel<<<DD / 16, 256>>>(nullptr, Wv, out, 1);
}

// round 5
// speedup vs baseline: 1.3382x; 1.3382x over previous
#include <cuda_runtime.h>
#include <cuda_bf16.h>

#define BB 16
#define SS 4096
#define DD 1024

#define GSPLIT 32      // split-K for the weight GEMVs
#define ATT_SPLIT 64   // 64-row sequence tiles (grid 64 x 16)

// ---------------- scratch (device globals; no allocations) ----------------
__device__ float g_q_part[GSPLIT][BB * DD];
__device__ float g_q[BB * DD];
__device__ float g_qk[BB * DD];
__device__ float g_esum_part[BB][ATT_SPLIT];
__device__ float g_ctx_part[ATT_SPLIT][BB * DD];
__device__ float g_ctx[BB * DD];
__device__ float g_out_part[GSPLIT][BB * DD];

// ---------------------------------------------------------------------------
// Split-K batched GEMV partials: part[split][b*D+h] = sum_{i in chunk} X[b,i]*W[i,h]
// grid (DD/128 = 8, GSPLIT = 32) = 256 blocks, block 128.
// Warp reads 128B of W per iter (coalesced); X chunk cached in smem.
// ---------------------------------------------------------------------------
__global__ void __launch_bounds__(128) gemv_part_kernel(const float* __restrict__ X,
                                                        const float* __restrict__ W,
                                                        float* __restrict__ part) {
    const int h  = blockIdx.x * 128 + threadIdx.x;
    const int IR = DD / GSPLIT;                     // 32
    const int i0 = blockIdx.y * IR;

    __shared__ float xs[BB][DD / GSPLIT];
    for (int t = threadIdx.x; t < BB * IR; t += 128) {
        int b = t >> 5, ii = t & 31;
        xs[b][ii] = X[b * DD + i0 + ii];
    }
    __syncthreads();

    float acc[BB];
#pragma unroll
    for (int b = 0; b < BB; b++) acc[b] = 0.f;

#pragma unroll 4
    for (int ii = 0; ii < IR; ii++) {
        float w = W[(size_t)(i0 + ii) * DD + h];
#pragma unroll
        for (int b = 0; b < BB; b++) acc[b] += xs[b][ii] * w;
    }

    float* p = part + (size_t)blockIdx.y * (BB * DD);
#pragma unroll
    for (int b = 0; b < BB; b++) p[b * DD + h] = acc[b];
}

// ---------------------------------------------------------------------------
// Sum GSPLIT partials (fixed order -> deterministic). grid 128, block 128.
// ---------------------------------------------------------------------------
__global__ void __launch_bounds__(128) reduce32_kernel(const float* __restrict__ part,
                                                       float* __restrict__ out) {
    const int idx = blockIdx.x * 128 + threadIdx.x;
    float s = 0.f;
#pragma unroll
    for (int k = 0; k < GSPLIT; k++) s += part[(size_t)k * (BB * DD) + idx];
    out[idx] = s;
}

// ---------------------------------------------------------------------------
// qk[b,i] = sum_h Wk[i,h] * q[b,h]   (warp per row i, float4 loads)
// grid 128, block 256 (8 warps)
// ---------------------------------------------------------------------------
__global__ void qk_kernel(const float* __restrict__ Wk) {
    const int warp = threadIdx.x >> 5;
    const int lane = threadIdx.x & 31;
    const int i = blockIdx.x * 8 + warp;

    __shared__ __align__(16) float qs[BB][DD];
    for (int t = threadIdx.x; t < BB * DD / 4; t += 256) {
        ((float4*)&qs[0][0])[t] = ((const float4*)g_q)[t];
    }
    __syncthreads();

    const float4* wrow = (const float4*)(Wk + (size_t)i * DD);

    float acc[BB];
#pragma unroll
    for (int b = 0; b < BB; b++) acc[b] = 0.f;

#pragma unroll
    for (int c = 0; c < DD / 4; c += 32) {
        float4 w4 = wrow[c + lane];
        int h = (c + lane) * 4;
#pragma unroll
        for (int b = 0; b < BB; b++) {
            acc[b] += w4.x * qs[b][h] + w4.y * qs[b][h + 1]
                    + w4.z * qs[b][h + 2] + w4.w * qs[b][h + 3];
        }
    }
#pragma unroll
    for (int b = 0; b < BB; b++) {
        float v = acc[b];
#pragma unroll
        for (int o = 16; o > 0; o >>= 1) v += __shfl_down_sync(0xffffffffu, v, o);
        if (lane == 0) g_qk[b * DD + i] = v;
    }
}

// ---------------------------------------------------------------------------
// Fused attention over a 64-row tile of one batch (R3 structure).
// __launch_bounds__(256, 7): <=36 regs -> 7 blocks/SM -> 1036 resident -> the
// full 1024-block grid runs as ONE wave (kills the R3 tail).
// grid (64, 16), block 256.
// ---------------------------------------------------------------------------
__global__ void __launch_bounds__(256, 7) attn_fused_kernel(const float* __restrict__ key,
                                                            const float* __restrict__ value) {
    const int b  = blockIdx.y;
    const int s0 = blockIdx.x * 64;
    const int warp = threadIdx.x >> 5;
    const int lane = threadIdx.x & 31;

    __shared__ __align__(16) float qk_s[DD];
    __shared__ float w_s[64];
    __shared__ float red[8];

    ((float4*)qk_s)[threadIdx.x] = ((const float4*)(g_qk + b * DD))[threadIdx.x];
    __syncthreads();

    const float4* qrow = (const float4*)qk_s;
    const float4* kbase = (const float4*)(key + ((size_t)b * SS + s0) * DD);

    // Phase A: 8 rows per warp, processed as 4 pairs
    float esum = 0.f;
#pragma unroll
    for (int p = 0; p < 4; p++) {
        const int r0 = warp * 8 + p * 2;
        const int r1 = r0 + 1;
        const float4* k0 = kbase + (size_t)r0 * (DD / 4);
        const float4* k1 = kbase + (size_t)r1 * (DD / 4);

        float a0 = 0.f, a1 = 0.f;
#pragma unroll
        for (int c = 0; c < DD / 4; c += 32) {
            float4 ka = __ldcs(&k0[c + lane]);
            float4 kb = __ldcs(&k1[c + lane]);
            float4 q4 = qrow[c + lane];
            a0 += ka.x * q4.x + ka.y * q4.y + ka.z * q4.z + ka.w * q4.w;
            a1 += kb.x * q4.x + kb.y * q4.y + kb.z * q4.z + kb.w * q4.w;
        }
#pragma unroll
        for (int o = 16; o > 0; o >>= 1) {
            a0 += __shfl_down_sync(0xffffffffu, a0, o);
            a1 += __shfl_down_sync(0xffffffffu, a1, o);
        }
        if (lane == 0) {
            float e0 = expf(a0 * 0.03125f);   // 1/sqrt(1024); bounded, no max shift
            float e1 = expf(a1 * 0.03125f);
            w_s[r0] = e0;
            w_s[r1] = e1;
            esum += e0 + e1;
        }
    }
    if (lane == 0) red[warp] = esum;
    __syncthreads();

    if (threadIdx.x == 0) {
        float s = 0.f;
#pragma unroll
        for (int w = 0; w < 8; w++) s += red[w];
        g_esum_part[b][blockIdx.x] = s;
    }

    // Phase B: thread owns one float4 of the 1024 output dims
    const float4* vbase = (const float4*)(value + ((size_t)b * SS + s0) * DD);
    const int i4 = threadIdx.x;

    float4 acc = make_float4(0.f, 0.f, 0.f, 0.f);
#pragma unroll 16
    for (int ss = 0; ss < 64; ss++) {
        float w = w_s[ss];
        float4 v = __ldcs(&vbase[(size_t)ss * (DD / 4) + i4]);
        acc.x += w * v.x; acc.y += w * v.y; acc.z += w * v.z; acc.w += w * v.w;
    }
    ((float4*)g_ctx_part[blockIdx.x])[b * (DD / 4) + i4] = acc;
}

// ---------------------------------------------------------------------------
// ctx reduce + softmax normalization, k-parallel.
// grid 512, block 256: block owns 32 idx; 8 warps each sum 8 of 64 partials.
// ---------------------------------------------------------------------------
__global__ void __launch_bounds__(256) reduce_ctx_kernel() {
    const int i   = threadIdx.x & 31;
    const int kk  = threadIdx.x >> 5;          // 0..7
    const int idx = blockIdx.x * 32 + i;
    const int b   = blockIdx.x >> 5;           // 32 blocks per batch

    __shared__ float red[8][32];
    __shared__ float s_inv;

    if (kk == 0) {   // warp 0 computes 1/sum(exp) for this batch
        float e = g_esum_part[b][i] + g_esum_part[b][i + 32];
#pragma unroll
        for (int o = 16; o > 0; o >>= 1) e += __shfl_down_sync(0xffffffffu, e, o);
        if (i == 0) s_inv = 1.f / e;
    }

    float s = 0.f;
#pragma unroll
    for (int m = 0; m < 8; m++) s += g_ctx_part[kk * 8 + m][idx];
    red[kk][i] = s;
    __syncthreads();

    if (kk == 0) {
        float t = 0.f;
#pragma unroll
        for (int m = 0; m < 8; m++) t += red[m][i];
        g_ctx[idx] = t * s_inv;
    }
}

// ---------------------------------------------------------------------------
extern "C" void kernel_launch(void* const* d_in, const int* in_sizes, int n_in,
                              void* d_out, int out_size) {
    const float* key   = (const float*)d_in[0];
    const float* query = (const float*)d_in[1];
    const float* value = (const float*)d_in[2];
    const float* Wk    = (const float*)d_in[3];
    const float* Wq    = (const float*)d_in[4];
    const float* Wv    = (const float*)d_in[5];
    float* out = (float*)d_out;

    float *d_q, *d_qpart, *d_opart, *d_ctx;
    cudaGetSymbolAddress((void**)&d_q, g_q);
    cudaGetSymbolAddress((void**)&d_qpart, g_q_part);
    cudaGetSymbolAddress((void**)&d_opart, g_out_part);
    cudaGetSymbolAddress((void**)&d_ctx, g_ctx);

    // q = query @ Wq
    gemv_part_kernel<<<dim3(DD / 128, GSPLIT), 128>>>(query, Wq, d_qpart);
    reduce32_kernel<<<BB * DD / 128, 128>>>(d_qpart, d_q);
    // qk[b] = Wk @ q[b]
    qk_kernel<<<DD / 8, 256>>>(Wk);
    // fused: scores -> exp -> weighted value partials (both big passes)
    attn_fused_kernel<<<dim3(ATT_SPLIT, BB), 256>>>(key, value);
    // ctx = (sum partials) / (sum exp)
    reduce_ctx_kernel<<<512, 256>>>();
    // out = ctx @ Wv
    gemv_part_kernel<<<dim3(DD / 128, GSPLIT), 128>>>(d_ctx, Wv, d_opart);
    reduce32_kernel<<<BB * DD / 128, 128>>>(d_opart, out);
}

// round 6
// speedup vs baseline: 1.3480x; 1.0073x over previous
#include <cuda_runtime.h>
#include <cuda_bf16.h>

#define BB 16
#define SS 4096
#define DD 1024

#define GSPLIT 32      // split-K for the weight GEMVs
#define ATT_SPLIT 64   // 64-row sequence tiles (grid 64 x 16)
#define PGRID 256      // blocks in prep/finish kernels (must all be resident)

// ---------------- scratch (device globals; no allocations) ----------------
__device__ float g_q_part[GSPLIT][BB * DD];
__device__ float g_q[BB * DD];
__device__ float g_qk[BB * DD];
__device__ float g_esum_part[BB][ATT_SPLIT];
__device__ float g_ctx_part[ATT_SPLIT][BB * DD];
__device__ float g_ctx[BB * DD];
__device__ float g_out_part[GSPLIT][BB * DD];
__device__ unsigned g_ctr[4];   // zero-initialized; restored to 0 on every exit

// ---------------------------------------------------------------------------
// Device-wide barrier for a PGRID-block kernel where all blocks are resident.
// ---------------------------------------------------------------------------
__device__ __forceinline__ void grid_barrier(unsigned* c) {
    __syncthreads();
    if (threadIdx.x == 0) {
        __threadfence();
        atomicAdd(c, 1u);
        while (atomicAdd(c, 0u) < PGRID) { }
        __threadfence();
    }
    __syncthreads();
}

// Last block out resets all counters so the next graph replay starts clean.
__device__ __forceinline__ void barrier_reset_exit() {
    __syncthreads();
    if (threadIdx.x == 0) {
        __threadfence();
        unsigned old = atomicAdd(&g_ctr[3], 1u);
        if (old == PGRID - 1) {
            atomicExch(&g_ctr[0], 0u);
            atomicExch(&g_ctr[1], 0u);
            atomicExch(&g_ctr[2], 0u);
            atomicExch(&g_ctr[3], 0u);
        }
    }
}

// ---------------------------------------------------------------------------
// PREP: (1) q partials = query @ Wq (split-K), (2) reduce -> g_q,
//       (3) qk[b,i] = sum_h Wk[i,h] * q[b,h].
// grid 256, block 128. smem 64KB (qs) reused as xs in phase 1.
// ---------------------------------------------------------------------------
__global__ void __launch_bounds__(128) prep_kernel(const float* __restrict__ query,
                                                   const float* __restrict__ Wq,
                                                   const float* __restrict__ Wk) {
    __shared__ __align__(16) float qs[BB][DD];   // 64 KB
    const int tid = threadIdx.x;
    const int bid = blockIdx.x;

    // ---- Phase 1: q partials. bid -> (hchunk = bid&7, split = bid>>3) ----
    {
        const int h  = (bid & 7) * 128 + tid;
        const int sp = bid >> 3;
        const int i0 = sp * (DD / GSPLIT);        // 32 rows per split
        float* xs = &qs[0][0];                    // 16*32 floats

        for (int t = tid; t < BB * 32; t += 128) {
            int b = t >> 5, ii = t & 31;
            xs[t] = query[b * DD + i0 + ii];
        }
        __syncthreads();

        float acc[BB];
#pragma unroll
        for (int b = 0; b < BB; b++) acc[b] = 0.f;
#pragma unroll 4
        for (int ii = 0; ii < 32; ii++) {
            float w = Wq[(size_t)(i0 + ii) * DD + h];
#pragma unroll
            for (int b = 0; b < BB; b++) acc[b] += xs[b * 32 + ii] * w;
        }
#pragma unroll
        for (int b = 0; b < BB; b++) g_q_part[sp][b * DD + h] = acc[b];
    }
    grid_barrier(&g_ctr[0]);

    // ---- Phase 2: reduce 32 partials -> g_q (16384 elems, 32768 threads) ----
    {
        const int idx = bid * 128 + tid;
        if (idx < BB * DD) {
            float s = 0.f;
#pragma unroll
            for (int k = 0; k < GSPLIT; k++) s += g_q_part[k][idx];
            g_q[idx] = s;
        }
    }
    grid_barrier(&g_ctr[1]);

    // ---- Phase 3: qk. warp per row i; block owns rows bid*4 .. bid*4+3 ----
    {
        for (int t = tid; t < BB * DD / 4; t += 128)
            ((float4*)&qs[0][0])[t] = ((const float4*)g_q)[t];
        __syncthreads();

        const int warp = tid >> 5;
        const int lane = tid & 31;
        const int i = bid * 4 + warp;
        const float4* wrow = (const float4*)(Wk + (size_t)i * DD);

        float acc[BB];
#pragma unroll
        for (int b = 0; b < BB; b++) acc[b] = 0.f;

#pragma unroll
        for (int c = 0; c < DD / 4; c += 32) {
            float4 w4 = wrow[c + lane];
            int h = (c + lane) * 4;
#pragma unroll
            for (int b = 0; b < BB; b++) {
                acc[b] += w4.x * qs[b][h] + w4.y * qs[b][h + 1]
                        + w4.z * qs[b][h + 2] + w4.w * qs[b][h + 3];
            }
        }
#pragma unroll
        for (int b = 0; b < BB; b++) {
            float v = acc[b];
#pragma unroll
            for (int o = 16; o > 0; o >>= 1) v += __shfl_down_sync(0xffffffffu, v, o);
            if (lane == 0) g_qk[b * DD + i] = v;
        }
    }
    barrier_reset_exit();
}

// ---------------------------------------------------------------------------
// Fused attention over a 64-row tile of one batch (R3 config: no min-blocks).
// grid (64, 16), block 256.
// ---------------------------------------------------------------------------
__global__ void __launch_bounds__(256) attn_fused_kernel(const float* __restrict__ key,
                                                         const float* __restrict__ value) {
    const int b  = blockIdx.y;
    const int s0 = blockIdx.x * 64;
    const int warp = threadIdx.x >> 5;
    const int lane = threadIdx.x & 31;

    __shared__ __align__(16) float qk_s[DD];
    __shared__ float w_s[64];
    __shared__ float red[8];

    ((float4*)qk_s)[threadIdx.x] = ((const float4*)(g_qk + b * DD))[threadIdx.x];
    __syncthreads();

    const float4* qrow = (const float4*)qk_s;
    const float4* kbase = (const float4*)(key + ((size_t)b * SS + s0) * DD);

    // Phase A: 8 rows per warp, processed as 4 pairs
    float esum = 0.f;
#pragma unroll
    for (int p = 0; p < 4; p++) {
        const int r0 = warp * 8 + p * 2;
        const int r1 = r0 + 1;
        const float4* k0 = kbase + (size_t)r0 * (DD / 4);
        const float4* k1 = kbase + (size_t)r1 * (DD / 4);

        float a0 = 0.f, a1 = 0.f;
#pragma unroll
        for (int c = 0; c < DD / 4; c += 32) {
            float4 ka = __ldcs(&k0[c + lane]);
            float4 kb = __ldcs(&k1[c + lane]);
            float4 q4 = qrow[c + lane];
            a0 += ka.x * q4.x + ka.y * q4.y + ka.z * q4.z + ka.w * q4.w;
            a1 += kb.x * q4.x + kb.y * q4.y + kb.z * q4.z + kb.w * q4.w;
        }
#pragma unroll
        for (int o = 16; o > 0; o >>= 1) {
            a0 += __shfl_down_sync(0xffffffffu, a0, o);
            a1 += __shfl_down_sync(0xffffffffu, a1, o);
        }
        if (lane == 0) {
            float e0 = expf(a0 * 0.03125f);   // 1/sqrt(1024); bounded, no max shift
            float e1 = expf(a1 * 0.03125f);
            w_s[r0] = e0;
            w_s[r1] = e1;
            esum += e0 + e1;
        }
    }
    if (lane == 0) red[warp] = esum;
    __syncthreads();

    if (threadIdx.x == 0) {
        float s = 0.f;
#pragma unroll
        for (int w = 0; w < 8; w++) s += red[w];
        g_esum_part[b][blockIdx.x] = s;
    }

    // Phase B: thread owns one float4 of the 1024 output dims
    const float4* vbase = (const float4*)(value + ((size_t)b * SS + s0) * DD);
    const int i4 = threadIdx.x;

    float4 acc = make_float4(0.f, 0.f, 0.f, 0.f);
#pragma unroll 16
    for (int ss = 0; ss < 64; ss++) {
        float w = w_s[ss];
        float4 v = __ldcs(&vbase[(size_t)ss * (DD / 4) + i4]);
        acc.x += w * v.x; acc.y += w * v.y; acc.z += w * v.z; acc.w += w * v.w;
    }
    ((float4*)g_ctx_part[blockIdx.x])[b * (DD / 4) + i4] = acc;
}

// ---------------------------------------------------------------------------
// FINISH: (1) ctx = (sum tile partials) / (sum exp), (2) out partials =
//         ctx @ Wv (split-K), (3) reduce -> d_out.
// grid 256, block 128.
// ---------------------------------------------------------------------------
__global__ void __launch_bounds__(128) finish_kernel(const float* __restrict__ Wv,
                                                     float* __restrict__ out) {
    __shared__ float xs[BB][DD / GSPLIT];   // 2 KB
    const int tid = threadIdx.x;
    const int bid = blockIdx.x;

    // ---- Phase 1: normalize ctx (warp-uniform b; 16384 elems) ----
    {
        const int idx = bid * 128 + tid;
        if (idx < BB * DD) {
            const int b = idx >> 10;          // uniform within warp
            const int lane = tid & 31;
            float e = g_esum_part[b][lane] + g_esum_part[b][lane + 32];
#pragma unroll
            for (int o = 16; o > 0; o >>= 1) e += __shfl_down_sync(0xffffffffu, e, o);
            const float inv = 1.f / __shfl_sync(0xffffffffu, e, 0);

            float s = 0.f;
#pragma unroll
            for (int k = 0; k < ATT_SPLIT; k++) s += g_ctx_part[k][idx];
            g_ctx[idx] = s * inv;
        }
    }
    grid_barrier(&g_ctr[0]);

    // ---- Phase 2: out partials. bid -> (hchunk = bid&7, split = bid>>3) ----
    {
        const int h  = (bid & 7) * 128 + tid;
        const int sp = bid >> 3;
        const int i0 = sp * (DD / GSPLIT);

        for (int t = tid; t < BB * 32; t += 128) {
            int b = t >> 5, ii = t & 31;
            (&xs[0][0])[t] = g_ctx[b * DD + i0 + ii];
        }
        __syncthreads();

        float acc[BB];
#pragma unroll
        for (int b = 0; b < BB; b++) acc[b] = 0.f;
#pragma unroll 4
        for (int ii = 0; ii < 32; ii++) {
            float w = Wv[(size_t)(i0 + ii) * DD + h];
#pragma unroll
            for (int b = 0; b < BB; b++) acc[b] += xs[b][ii] * w;
        }
#pragma unroll
        for (int b = 0; b < BB; b++) g_out_part[sp][b * DD + h] = acc[b];
    }
    grid_barrier(&g_ctr[1]);

    // ---- Phase 3: reduce 32 partials -> d_out ----
    {
        const int idx = bid * 128 + tid;
        if (idx < BB * DD) {
            float s = 0.f;
#pragma unroll
            for (int k = 0; k < GSPLIT; k++) s += g_out_part[k][idx];
            out[idx] = s;
        }
    }
    barrier_reset_exit();
}

// ---------------------------------------------------------------------------
extern "C" void kernel_launch(void* const* d_in, const int* in_sizes, int n_in,
                              void* d_out, int out_size) {
    const float* key   = (const float*)d_in[0];
    const float* query = (const float*)d_in[1];
    const float* value = (const float*)d_in[2];
    const float* Wk    = (const float*)d_in[3];
    const float* Wq    = (const float*)d_in[4];
    const float* Wv    = (const float*)d_in[5];
    float* out = (float*)d_out;

    // q = query@Wq ; q reduce ; qk = Wk@q        (one kernel, 2 grid barriers)
    prep_kernel<<<PGRID, 128>>>(query, Wq, Wk);
    // fused: scores -> exp -> weighted value partials (both big passes)
    attn_fused_kernel<<<dim3(ATT_SPLIT, BB), 256>>>(key, value);
    // ctx normalize ; out = ctx@Wv ; out reduce  (one kernel, 2 grid barriers)
    finish_kernel<<<PGRID, 128>>>(Wv, out);
}